// round 14
// baseline (speedup 1.0000x reference)
#include <cuda_runtime.h>
#include <cuda_fp16.h>
#include <cstdint>

// Problem dims
#define NI 16384
#define NC 4096
#define ND 256
#define KD 128              // screened dims
#define KK 256              // fused screen-GEMM K = 2*KD

// Screen: skip pair when fp16 partial d2 (lower bound of full d2, slack 1.0)
// >= TSCREEN. Partial ~ N(42.7, 6.9^2) -> z=4.16 -> per-warp trigger ~3%.
#define TSCREEN 14.0f

// Tiling
#define BM 128
#define BN 128
#define BK 64               // fp16 elems per k-chunk = 128 bytes/row
#define KITERS (KK / BK)    // 4
#define NSTAGE 2
#define CHUNKB 128          // bytes per row per chunk

#define A_TILE_BYTES (BM * CHUNKB)       // 16384
#define B_TILE_BYTES (BN * CHUNKB)       // 16384
#define STAGE_BYTES (A_TILE_BYTES + B_TILE_BYTES)   // 32768
#define SM_A(st) (1024 + (st) * STAGE_BYTES)
#define SM_B(st) (SM_A(st) + A_TILE_BYTES)
#define SMEM_BYTES (1024 + NSTAGE * STAGE_BYTES)    // 66560 -> 3 CTAs/SM

// Device scratch, k-chunk-major with SW128 swizzle baked in
__device__ uint8_t g_A[(size_t)KITERS * NI * CHUNKB];   // 8.4 MB
__device__ uint8_t g_B[(size_t)KITERS * NC * CHUNKB];   // 2.1 MB
__device__ float g_csum[NC];                            // sum over d<128
__device__ float g_score[NI];

// ---------------------------------------------------------------- helpers
__device__ __forceinline__ uint32_t smem_u32(const void* p) {
    uint32_t a;
    asm("{ .reg .u64 t; cvta.to.shared.u64 t, %1; cvt.u32.u64 %0, t; }" : "=r"(a) : "l"(p));
    return a;
}
#define MBAR_INIT(a, n) \
    asm volatile("mbarrier.init.shared.b64 [%0], %1;" :: "r"(a), "r"(n) : "memory")
#define MBAR_EXPECT_TX(a, bytes) \
    asm volatile("mbarrier.arrive.expect_tx.shared.b64 _, [%0], %1;" :: "r"(a), "r"(bytes) : "memory")
#define MBAR_WAIT(a, ph) do {                                                     \
    uint32_t _m = (a), _p = (ph), _d;                                             \
    asm volatile("{ .reg .pred p; mbarrier.try_wait.parity.acquire.cta.shared::cta.b64 p, [%1], %2; selp.b32 %0,1,0,p; }" \
                 : "=r"(_d) : "r"(_m), "r"(_p) : "memory");                       \
    if (!_d) {                                                                    \
        asm volatile("{ .reg .pred P; W%=: mbarrier.try_wait.parity.acquire.cta.shared::cta.b64 P, [%0], %1, 0x989680; @P bra.uni D%=; bra.uni W%=; D%=: }" \
                     :: "r"(_m), "r"(_p) : "memory");                             \
    } } while (0)
#define CP_BULK(dst, src, bytes, mbar) \
    asm volatile("cp.async.bulk.shared::cluster.global.mbarrier::complete_tx::bytes " \
                 "[%0], [%1], %2, [%3];" \
                 :: "r"(dst), "l"(src), "r"(bytes), "r"(mbar) : "memory")

__device__ __forceinline__ void ldm_x4(uint32_t* r, uint32_t addr) {
    asm volatile("ldmatrix.sync.aligned.m8n8.x4.shared.b16 {%0,%1,%2,%3}, [%4];"
                 : "=r"(r[0]), "=r"(r[1]), "=r"(r[2]), "=r"(r[3]) : "r"(addr));
}
__device__ __forceinline__ void mma_f16acc(uint32_t* c, const uint32_t* a, const uint32_t* b) {
    asm volatile(
        "mma.sync.aligned.m16n8k16.row.col.f16.f16.f16.f16 "
        "{%0,%1}, {%2,%3,%4,%5}, {%6,%7}, {%0,%1};"
        : "+r"(c[0]), "+r"(c[1])
        : "r"(a[0]), "r"(a[1]), "r"(a[2]), "r"(a[3]), "r"(b[0]), "r"(b[1]));
}

// ---------------------------------------------------------------- fused prep
// Blocks [0, NA) handle A (+score zeroing); blocks [NA, NA+NB) handle B.
#define NA ((NI * KD + 255) / 256)          // 8192
#define NB ((NC + 7) / 8)                   // 512 (8 warps per block)

__global__ void prep_kernel(const float* __restrict__ x,
                            const float* __restrict__ centers,
                            const float* __restrict__ sigmas) {
    if (blockIdx.x < NA) {
        int idx = blockIdx.x * 256 + threadIdx.x;
        if (idx >= NI * KD) return;
        if (idx < NI) g_score[idx] = 0.f;
        int n = idx >> 7;            // / 128
        int d = idx & (KD - 1);
        float v = x[n * ND + d];
        uint32_t sw = ((uint32_t)(n & 7)) << 4;
        int kch = d >> 6, e = d & 63;            // kch 0..1
        *(__half*)(g_A + ((size_t)kch * NI + n) * CHUNKB + ((2 * e) ^ sw)) =
            __float2half(v * v);
        *(__half*)(g_A + ((size_t)(2 + kch) * NI + n) * CHUNKB + ((2 * e) ^ sw)) =
            __float2half(v);
    } else {
        int c = (blockIdx.x - NA) * 8 + (threadIdx.x >> 5);
        int lane = threadIdx.x & 31;
        if (c >= NC) return;
        uint32_t sw = ((uint32_t)(c & 7)) << 4;
        float acc = 0.f;
        #pragma unroll
        for (int d = lane; d < KD; d += 32) {
            float s   = sigmas[c * ND + d];
            float ce  = centers[c * ND + d];
            float inv = 1.0f / (2.0f * s * s);
            int kch = d >> 6, e = d & 63;
            *(__half*)(g_B + ((size_t)kch * NC + c) * CHUNKB + ((2 * e) ^ sw)) =
                __float2half(inv);
            *(__half*)(g_B + ((size_t)(2 + kch) * NC + c) * CHUNKB + ((2 * e) ^ sw)) =
                __float2half(-2.0f * ce * inv);
            acc = fmaf(ce * ce, inv, acc);
        }
        #pragma unroll
        for (int m = 16; m; m >>= 1) acc += __shfl_xor_sync(0xffffffffu, acc, m);
        if (lane == 0) g_csum[c] = acc;
    }
}

// ---------------------------------------------------------------- main kernel
__global__ void __launch_bounds__(256, 3)
rbf_mma_kernel(const float* __restrict__ x,
               const float* __restrict__ centers,
               const float* __restrict__ sigmas,
               const float* __restrict__ w_lin) {
    extern __shared__ char smem[];
    const uint32_t smem_base = smem_u32(smem);
    const int tid  = threadIdx.x;
    const int lane = tid & 31;
    const int wid  = tid >> 5;
    const int wm   = wid >> 2;      // 0..1  (M)
    const int wn   = wid & 3;       // 0..3  (N)
    const int bn   = blockIdx.x;    // center tile
    const int bm   = blockIdx.y;    // input tile

    if (tid == 0) {
        MBAR_INIT(smem_base + 0, 1);
        MBAR_INIT(smem_base + 8, 1);
    }
    __syncthreads();

    auto issue_stage = [&](int st, int kiter) {
        uint32_t mb = smem_base + st * 8;
        MBAR_EXPECT_TX(mb, STAGE_BYTES);
        const uint8_t* srcA = g_A + ((size_t)kiter * NI + bm * BM) * CHUNKB;
        const uint8_t* srcB = g_B + ((size_t)kiter * NC + bn * BN) * CHUNKB;
        CP_BULK(smem_base + SM_A(st), (const void*)srcA, A_TILE_BYTES, mb);
        CP_BULK(smem_base + SM_B(st), (const void*)srcB, B_TILE_BYTES, mb);
    };

    if (tid == 0) {
        issue_stage(0, 0);
        issue_stage(1, 1);
    }

    // fp16 accumulators: 2 regs per m16n8 tile -> 32 regs
    uint32_t acc[4][4][2];
    #pragma unroll
    for (int mt = 0; mt < 4; mt++)
        #pragma unroll
        for (int nt = 0; nt < 4; nt++) { acc[mt][nt][0] = 0u; acc[mt][nt][1] = 0u; }

    // Hoisted, stage-relative fragment address components
    const int aRow  = wm * 64 + (lane & 15);        // + mt*16
    const uint32_t aOff = ((lane >> 4) << 4);
    const int bG    = lane >> 3;
    const int bRowBase = wn * 32 + (bG >> 1) * 8 + (lane & 7);   // + p*16
    const uint32_t bOff = ((bG & 1) << 4);

    #pragma unroll
    for (int k = 0; k < KITERS; k++) {              // fully unrolled
        const int st = k & 1;
        MBAR_WAIT(smem_base + st * 8, (k >> 1) & 1);

        const uint32_t aBase = smem_base + SM_A(st);
        const uint32_t bBase = smem_base + SM_B(st);
        #pragma unroll
        for (int kc = 0; kc < 4; kc++) {           // 4 x k16 per stage
            uint32_t a[4][4], b[4][2];
            #pragma unroll
            for (int mt = 0; mt < 4; mt++) {
                int row = aRow + mt * 16;
                uint32_t boff = kc * 32 + aOff;
                ldm_x4(a[mt], aBase + row * CHUNKB + (boff ^ ((row & 7) << 4)));
            }
            #pragma unroll
            for (int p = 0; p < 2; p++) {
                int trow = bRowBase + p * 16;
                uint32_t boff = kc * 32 + bOff;
                uint32_t bp[4];
                ldm_x4(bp, bBase + trow * CHUNKB + (boff ^ ((trow & 7) << 4)));
                b[2 * p][0] = bp[0]; b[2 * p][1] = bp[1];
                b[2 * p + 1][0] = bp[2]; b[2 * p + 1][1] = bp[3];
            }
            #pragma unroll
            for (int mt = 0; mt < 4; mt++)
                #pragma unroll
                for (int nt = 0; nt < 4; nt++)
                    mma_f16acc(acc[mt][nt], a[mt], b[nt]);
        }

        __syncthreads();
        if (tid == 0 && k + NSTAGE < KITERS) issue_stage(st, k + NSTAGE);
    }

    // ---------------- epilogue: p = partial d2 over 128 dims (lower bound).
    const int cBase = bn * BN + wn * 32;
    float cs[4][2];
    #pragma unroll
    for (int nt = 0; nt < 4; nt++)
        #pragma unroll
        for (int j = 0; j < 2; j++)
            cs[nt][j] = __ldg(&g_csum[cBase + nt * 8 + (lane & 3) * 2 + j]);

    float mn = 1e30f;
    #pragma unroll
    for (int mt = 0; mt < 4; mt++)
        #pragma unroll
        for (int nt = 0; nt < 4; nt++)
            #pragma unroll
            for (int h = 0; h < 2; h++) {
                __half2 hv = *reinterpret_cast<__half2*>(&acc[mt][nt][h]);
                mn = fminf(mn, __low2float(hv)  + cs[nt][0]);
                mn = fminf(mn, __high2float(hv) + cs[nt][1]);
            }

    if (__any_sync(0xffffffffu, mn < TSCREEN)) {    // ~3% of warps
        float rs[4][2];
        #pragma unroll
        for (int mt = 0; mt < 4; mt++) { rs[mt][0] = 0.f; rs[mt][1] = 0.f; }
        #pragma unroll 1
        for (int mt = 0; mt < 4; mt++)
            #pragma unroll 1
            for (int nt = 0; nt < 4; nt++)
                #pragma unroll 1
                for (int h = 0; h < 2; h++) {
                    __half2 hv = *reinterpret_cast<__half2*>(&acc[mt][nt][h]);
                    float pv[2] = { __low2float(hv)  + cs[nt][0],
                                    __high2float(hv) + cs[nt][1] };
                    #pragma unroll 1
                    for (int j = 0; j < 2; j++) {
                        if (pv[j] < TSCREEN) {
                            int row = bm * BM + wm * 64 + mt * 16 + h * 8 + (lane >> 2);
                            int col = cBase + nt * 8 + (lane & 3) * 2 + j;
                            float rest = 0.f;
                            #pragma unroll 4
                            for (int d = KD; d < ND; d++) {
                                float xv = x[row * ND + d];
                                float cv = centers[col * ND + d];
                                float sv = sigmas[col * ND + d];
                                float df = xv - cv;
                                rest += (df * df) / (2.0f * sv * sv);
                            }
                            float d2 = pv[j] + rest;
                            if (d2 < 60.f)
                                rs[mt][h] = fmaf(expf(-d2), __ldg(&w_lin[col]), rs[mt][h]);
                        }
                    }
                }
        #pragma unroll
        for (int mt = 0; mt < 4; mt++)
            #pragma unroll
            for (int h = 0; h < 2; h++) {
                float v = rs[mt][h];
                v += __shfl_xor_sync(0xffffffffu, v, 1);
                v += __shfl_xor_sync(0xffffffffu, v, 2);
                if ((lane & 3) == 0)
                    atomicAdd(&g_score[bm * BM + wm * 64 + mt * 16 + h * 8 + (lane >> 2)], v);
            }
    }
    // fast path: skipped mass bounded; g_score pre-zeroed
}

__global__ void finalize_kernel(const float* __restrict__ b_lin,
                                float* __restrict__ out) {
    int n = blockIdx.x * blockDim.x + threadIdx.x;
    if (n < NI) {
        float s = g_score[n] + b_lin[0];
        out[n] = 1.0f / (1.0f + __expf(-s));
    }
}

// ---------------------------------------------------------------- launch
extern "C" void kernel_launch(void* const* d_in, const int* in_sizes, int n_in,
                              void* d_out, int out_size) {
    const float* x       = (const float*)d_in[0];
    const float* centers = (const float*)d_in[1];
    const float* sigmas  = (const float*)d_in[2];
    const float* w_lin   = (const float*)d_in[3];
    const float* b_lin   = (const float*)d_in[4];
    float* out = (float*)d_out;

    cudaFuncSetAttribute(rbf_mma_kernel,
                         cudaFuncAttributeMaxDynamicSharedMemorySize, SMEM_BYTES);

    prep_kernel<<<NA + NB, 256>>>(x, centers, sigmas);
    dim3 grid(NC / BN, NI / BM);   // (32, 128)
    rbf_mma_kernel<<<grid, 256, SMEM_BYTES>>>(x, centers, sigmas, w_lin);
    finalize_kernel<<<NI / 256, 256>>>(b_lin, out);
}

// round 15
// speedup vs baseline: 1.3880x; 1.3880x over previous
#include <cuda_runtime.h>
#include <cuda_fp16.h>
#include <cstdint>

// Problem dims
#define NI 16384
#define NC 4096
#define ND 256
#define KD 128              // screened dims
#define KK 256              // fused screen-GEMM K = 2*KD

// Screen: skip pair when fp16 partial d2 (lower bound of full d2, slack 1.0)
// >= TSCREEN. Partial ~ N(42.7, 6.9^2) -> z=4.16 -> per-warp trigger ~3%.
#define TSCREEN 14.0f

// Tiling
#define BM 128
#define BN 128
#define BK 64               // fp16 elems per k-chunk = 128 bytes/row
#define KITERS (KK / BK)    // 4
#define NSTAGE 2
#define CHUNKB 128          // bytes per row per chunk

#define A_TILE_BYTES (BM * CHUNKB)       // 16384
#define B_TILE_BYTES (BN * CHUNKB)       // 16384
#define STAGE_BYTES (A_TILE_BYTES + B_TILE_BYTES)   // 32768
#define SM_A(st) (1024 + (st) * STAGE_BYTES)
#define SM_B(st) (SM_A(st) + A_TILE_BYTES)
#define SMEM_BYTES (1024 + NSTAGE * STAGE_BYTES)    // 66560 -> 3 CTAs/SM

// Device scratch, k-chunk-major with SW128 swizzle baked in
__device__ uint8_t g_A[(size_t)KITERS * NI * CHUNKB];   // 8.4 MB
__device__ uint8_t g_B[(size_t)KITERS * NC * CHUNKB];   // 2.1 MB
__device__ float g_csum[NC];                            // sum over d<128
__device__ float g_score[NI];

// ---------------------------------------------------------------- helpers
__device__ __forceinline__ uint32_t smem_u32(const void* p) {
    uint32_t a;
    asm("{ .reg .u64 t; cvta.to.shared.u64 t, %1; cvt.u32.u64 %0, t; }" : "=r"(a) : "l"(p));
    return a;
}
#define MBAR_INIT(a, n) \
    asm volatile("mbarrier.init.shared.b64 [%0], %1;" :: "r"(a), "r"(n) : "memory")
#define MBAR_EXPECT_TX(a, bytes) \
    asm volatile("mbarrier.arrive.expect_tx.shared.b64 _, [%0], %1;" :: "r"(a), "r"(bytes) : "memory")
#define MBAR_WAIT(a, ph) do {                                                     \
    uint32_t _m = (a), _p = (ph), _d;                                             \
    asm volatile("{ .reg .pred p; mbarrier.try_wait.parity.acquire.cta.shared::cta.b64 p, [%1], %2; selp.b32 %0,1,0,p; }" \
                 : "=r"(_d) : "r"(_m), "r"(_p) : "memory");                       \
    if (!_d) {                                                                    \
        asm volatile("{ .reg .pred P; W%=: mbarrier.try_wait.parity.acquire.cta.shared::cta.b64 P, [%0], %1, 0x989680; @P bra.uni D%=; bra.uni W%=; D%=: }" \
                     :: "r"(_m), "r"(_p) : "memory");                             \
    } } while (0)
#define CP_BULK(dst, src, bytes, mbar) \
    asm volatile("cp.async.bulk.shared::cluster.global.mbarrier::complete_tx::bytes " \
                 "[%0], [%1], %2, [%3];" \
                 :: "r"(dst), "l"(src), "r"(bytes), "r"(mbar) : "memory")

__device__ __forceinline__ void ldm_x4(uint32_t* r, uint32_t addr) {
    asm volatile("ldmatrix.sync.aligned.m8n8.x4.shared.b16 {%0,%1,%2,%3}, [%4];"
                 : "=r"(r[0]), "=r"(r[1]), "=r"(r[2]), "=r"(r[3]) : "r"(addr));
}
__device__ __forceinline__ void mma_f16acc(uint32_t* c, const uint32_t* a, const uint32_t* b) {
    asm volatile(
        "mma.sync.aligned.m16n8k16.row.col.f16.f16.f16.f16 "
        "{%0,%1}, {%2,%3,%4,%5}, {%6,%7}, {%0,%1};"
        : "+r"(c[0]), "+r"(c[1])
        : "r"(a[0]), "r"(a[1]), "r"(a[2]), "r"(a[3]), "r"(b[0]), "r"(b[1]));
}

// ---------------------------------------------------------------- fused prep
// Blocks [0, NA) handle A (+score zeroing); blocks [NA, NA+NB) handle B.
#define NA ((NI * KD + 255) / 256)          // 8192
#define NB ((NC + 7) / 8)                   // 512 (8 warps per block)

__global__ void prep_kernel(const float* __restrict__ x,
                            const float* __restrict__ centers,
                            const float* __restrict__ sigmas) {
    if (blockIdx.x < NA) {
        int idx = blockIdx.x * 256 + threadIdx.x;
        if (idx >= NI * KD) return;
        if (idx < NI) g_score[idx] = 0.f;
        int n = idx >> 7;            // / 128
        int d = idx & (KD - 1);
        float v = x[n * ND + d];
        uint32_t sw = ((uint32_t)(n & 7)) << 4;
        int kch = d >> 6, e = d & 63;            // kch 0..1
        *(__half*)(g_A + ((size_t)kch * NI + n) * CHUNKB + ((2 * e) ^ sw)) =
            __float2half(v * v);
        *(__half*)(g_A + ((size_t)(2 + kch) * NI + n) * CHUNKB + ((2 * e) ^ sw)) =
            __float2half(v);
    } else {
        int c = (blockIdx.x - NA) * 8 + (threadIdx.x >> 5);
        int lane = threadIdx.x & 31;
        if (c >= NC) return;
        uint32_t sw = ((uint32_t)(c & 7)) << 4;
        float acc = 0.f;
        #pragma unroll
        for (int d = lane; d < KD; d += 32) {
            float s   = sigmas[c * ND + d];
            float ce  = centers[c * ND + d];
            float inv = 1.0f / (2.0f * s * s);
            int kch = d >> 6, e = d & 63;
            *(__half*)(g_B + ((size_t)kch * NC + c) * CHUNKB + ((2 * e) ^ sw)) =
                __float2half(inv);
            *(__half*)(g_B + ((size_t)(2 + kch) * NC + c) * CHUNKB + ((2 * e) ^ sw)) =
                __float2half(-2.0f * ce * inv);
            acc = fmaf(ce * ce, inv, acc);
        }
        #pragma unroll
        for (int m = 16; m; m >>= 1) acc += __shfl_xor_sync(0xffffffffu, acc, m);
        if (lane == 0) g_csum[c] = acc;
    }
}

// ---------------------------------------------------------------- main kernel
__global__ void __launch_bounds__(256, 3)
rbf_mma_kernel(const float* __restrict__ x,
               const float* __restrict__ centers,
               const float* __restrict__ sigmas,
               const float* __restrict__ w_lin) {
    extern __shared__ char smem[];
    const uint32_t smem_base = smem_u32(smem);
    const int tid  = threadIdx.x;
    const int lane = tid & 31;
    const int wid  = tid >> 5;
    const int wm   = wid >> 2;      // 0..1  (M)
    const int wn   = wid & 3;       // 0..3  (N)
    const int bn   = blockIdx.x;    // center tile
    const int bm   = blockIdx.y;    // input tile

    if (tid == 0) {
        MBAR_INIT(smem_base + 0, 1);
        MBAR_INIT(smem_base + 8, 1);
    }
    __syncthreads();

    auto issue_stage = [&](int st, int kiter) {
        uint32_t mb = smem_base + st * 8;
        MBAR_EXPECT_TX(mb, STAGE_BYTES);
        const uint8_t* srcA = g_A + ((size_t)kiter * NI + bm * BM) * CHUNKB;
        const uint8_t* srcB = g_B + ((size_t)kiter * NC + bn * BN) * CHUNKB;
        CP_BULK(smem_base + SM_A(st), (const void*)srcA, A_TILE_BYTES, mb);
        CP_BULK(smem_base + SM_B(st), (const void*)srcB, B_TILE_BYTES, mb);
    };

    if (tid == 0) {
        issue_stage(0, 0);
        issue_stage(1, 1);
    }

    // fp16 accumulators: 2 regs per m16n8 tile -> 32 regs
    uint32_t acc[4][4][2];
    #pragma unroll
    for (int mt = 0; mt < 4; mt++)
        #pragma unroll
        for (int nt = 0; nt < 4; nt++) { acc[mt][nt][0] = 0u; acc[mt][nt][1] = 0u; }

    #pragma unroll 1
    for (int k = 0; k < KITERS; k++) {
        const int st = k & 1;
        MBAR_WAIT(smem_base + st * 8, (k >> 1) & 1);

        const uint32_t aBase = smem_base + SM_A(st);
        const uint32_t bBase = smem_base + SM_B(st);
        #pragma unroll
        for (int kc = 0; kc < 4; kc++) {           // 4 x k16 per stage
            uint32_t a[4][4], b[4][2];
            #pragma unroll
            for (int mt = 0; mt < 4; mt++) {
                int row = wm * 64 + mt * 16 + (lane & 15);
                uint32_t boff = kc * 32 + ((lane >> 4) << 4);
                uint32_t addr = aBase + row * CHUNKB + (boff ^ ((row & 7) << 4));
                ldm_x4(a[mt], addr);
            }
            #pragma unroll
            for (int p = 0; p < 2; p++) {
                int g = lane >> 3;            // 0..3: {t0 k0, t0 k8, t1 k0, t1 k8}
                int trow = wn * 32 + p * 16 + (g >> 1) * 8 + (lane & 7);
                uint32_t boff = kc * 32 + ((g & 1) << 4);
                uint32_t addr = bBase + trow * CHUNKB + (boff ^ ((trow & 7) << 4));
                uint32_t bp[4];
                ldm_x4(bp, addr);
                b[2 * p][0] = bp[0]; b[2 * p][1] = bp[1];
                b[2 * p + 1][0] = bp[2]; b[2 * p + 1][1] = bp[3];
            }
            #pragma unroll
            for (int mt = 0; mt < 4; mt++)
                #pragma unroll
                for (int nt = 0; nt < 4; nt++)
                    mma_f16acc(acc[mt][nt], a[mt], b[nt]);
        }

        // barrier only needed when this stage's buffer gets refilled
        if (k + NSTAGE < KITERS) {
            __syncthreads();
            if (tid == 0) issue_stage(st, k + NSTAGE);
        }
    }

    // ---------------- epilogue: p = partial d2 over 128 dims (lower bound).
    // Skip if p >= TSCREEN; else compute remaining 128 dims exactly (fp32).
    const int cBase = bn * BN + wn * 32;
    float cs[4][2];
    #pragma unroll
    for (int nt = 0; nt < 4; nt++)
        #pragma unroll
        for (int j = 0; j < 2; j++)
            cs[nt][j] = __ldg(&g_csum[cBase + nt * 8 + (lane & 3) * 2 + j]);

    float mn = 1e30f;
    #pragma unroll
    for (int mt = 0; mt < 4; mt++)
        #pragma unroll
        for (int nt = 0; nt < 4; nt++)
            #pragma unroll
            for (int h = 0; h < 2; h++) {
                __half2 hv = *reinterpret_cast<__half2*>(&acc[mt][nt][h]);
                mn = fminf(mn, __low2float(hv)  + cs[nt][0]);
                mn = fminf(mn, __high2float(hv) + cs[nt][1]);
            }

    if (__any_sync(0xffffffffu, mn < TSCREEN)) {    // ~3% of warps
        float rs[4][2];
        #pragma unroll
        for (int mt = 0; mt < 4; mt++) { rs[mt][0] = 0.f; rs[mt][1] = 0.f; }
        #pragma unroll 1
        for (int mt = 0; mt < 4; mt++)
            #pragma unroll 1
            for (int nt = 0; nt < 4; nt++)
                #pragma unroll 1
                for (int h = 0; h < 2; h++) {
                    __half2 hv = *reinterpret_cast<__half2*>(&acc[mt][nt][h]);
                    float pv[2] = { __low2float(hv)  + cs[nt][0],
                                    __high2float(hv) + cs[nt][1] };
                    #pragma unroll 1
                    for (int j = 0; j < 2; j++) {
                        if (pv[j] < TSCREEN) {
                            int row = bm * BM + wm * 64 + mt * 16 + h * 8 + (lane >> 2);
                            int col = cBase + nt * 8 + (lane & 3) * 2 + j;
                            float rest = 0.f;
                            #pragma unroll 4
                            for (int d = KD; d < ND; d++) {
                                float xv = x[row * ND + d];
                                float cv = centers[col * ND + d];
                                float sv = sigmas[col * ND + d];
                                float df = xv - cv;
                                rest += (df * df) / (2.0f * sv * sv);
                            }
                            float d2 = pv[j] + rest;
                            if (d2 < 60.f)
                                rs[mt][h] = fmaf(expf(-d2), __ldg(&w_lin[col]), rs[mt][h]);
                        }
                    }
                }
        #pragma unroll
        for (int mt = 0; mt < 4; mt++)
            #pragma unroll
            for (int h = 0; h < 2; h++) {
                float v = rs[mt][h];
                v += __shfl_xor_sync(0xffffffffu, v, 1);
                v += __shfl_xor_sync(0xffffffffu, v, 2);
                if ((lane & 3) == 0)
                    atomicAdd(&g_score[bm * BM + wm * 64 + mt * 16 + h * 8 + (lane >> 2)], v);
            }
    }
    // fast path: skipped mass bounded; g_score pre-zeroed
}

__global__ void finalize_kernel(const float* __restrict__ b_lin,
                                float* __restrict__ out) {
    int n = blockIdx.x * blockDim.x + threadIdx.x;
    if (n < NI) {
        float s = g_score[n] + b_lin[0];
        out[n] = 1.0f / (1.0f + __expf(-s));
    }
}

// ---------------------------------------------------------------- launch
extern "C" void kernel_launch(void* const* d_in, const int* in_sizes, int n_in,
                              void* d_out, int out_size) {
    const float* x       = (const float*)d_in[0];
    const float* centers = (const float*)d_in[1];
    const float* sigmas  = (const float*)d_in[2];
    const float* w_lin   = (const float*)d_in[3];
    const float* b_lin   = (const float*)d_in[4];
    float* out = (float*)d_out;

    cudaFuncSetAttribute(rbf_mma_kernel,
                         cudaFuncAttributeMaxDynamicSharedMemorySize, SMEM_BYTES);

    prep_kernel<<<NA + NB, 256>>>(x, centers, sigmas);
    dim3 grid(NC / BN, NI / BM);   // (32, 128)
    rbf_mma_kernel<<<grid, 256, SMEM_BYTES>>>(x, centers, sigmas, w_lin);
    finalize_kernel<<<NI / 256, 256>>>(b_lin, out);
}

// round 17
// speedup vs baseline: 1.4559x; 1.0489x over previous
#include <cuda_runtime.h>
#include <cuda_fp16.h>
#include <cstdint>

// Problem dims
#define NI 16384
#define NC 4096
#define ND 256
#define KD 128              // screened dims
#define KK 256              // fused screen-GEMM K = 2*KD

// Screen: skip pair when fp16 partial d2 (lower bound of full d2, slack 1.0)
// >= TSCREEN. Partial ~ N(42.7, 6.9^2) -> z=4.16 -> per-warp trigger ~3%.
#define TSCREEN 14.0f

// Tiling
#define BM 128
#define BN 128
#define BK 64               // fp16 elems per k-chunk = 128 bytes/row
#define KITERS (KK / BK)    // 4
#define NSTAGE 2
#define CHUNKB 128          // bytes per row per chunk

#define A_TILE_BYTES (BM * CHUNKB)       // 16384
#define B_TILE_BYTES (BN * CHUNKB)       // 16384
#define STAGE_BYTES (A_TILE_BYTES + B_TILE_BYTES)   // 32768
#define SM_A(st) (1024 + (st) * STAGE_BYTES)
#define SM_B(st) (SM_A(st) + A_TILE_BYTES)
#define SMEM_BYTES (1024 + NSTAGE * STAGE_BYTES)    // 66560 -> 3 CTAs/SM

// Device scratch, k-chunk-major with SW128 swizzle baked in
__device__ uint8_t g_A[(size_t)KITERS * NI * CHUNKB];   // 8.4 MB
__device__ uint8_t g_B[(size_t)KITERS * NC * CHUNKB];   // 2.1 MB
__device__ float g_csum[NC];                            // sum over d<128
__device__ float g_score[NI];

// ---------------------------------------------------------------- helpers
__device__ __forceinline__ uint32_t smem_u32(const void* p) {
    uint32_t a;
    asm("{ .reg .u64 t; cvta.to.shared.u64 t, %1; cvt.u32.u64 %0, t; }" : "=r"(a) : "l"(p));
    return a;
}
#define MBAR_INIT(a, n) \
    asm volatile("mbarrier.init.shared.b64 [%0], %1;" :: "r"(a), "r"(n) : "memory")
#define MBAR_EXPECT_TX(a, bytes) \
    asm volatile("mbarrier.arrive.expect_tx.shared.b64 _, [%0], %1;" :: "r"(a), "r"(bytes) : "memory")
#define MBAR_WAIT(a, ph) do {                                                     \
    uint32_t _m = (a), _p = (ph), _d;                                             \
    asm volatile("{ .reg .pred p; mbarrier.try_wait.parity.acquire.cta.shared::cta.b64 p, [%1], %2; selp.b32 %0,1,0,p; }" \
                 : "=r"(_d) : "r"(_m), "r"(_p) : "memory");                       \
    if (!_d) {                                                                    \
        asm volatile("{ .reg .pred P; W%=: mbarrier.try_wait.parity.acquire.cta.shared::cta.b64 P, [%0], %1, 0x989680; @P bra.uni D%=; bra.uni W%=; D%=: }" \
                     :: "r"(_m), "r"(_p) : "memory");                             \
    } } while (0)
#define CP_BULK(dst, src, bytes, mbar) \
    asm volatile("cp.async.bulk.shared::cluster.global.mbarrier::complete_tx::bytes " \
                 "[%0], [%1], %2, [%3];" \
                 :: "r"(dst), "l"(src), "r"(bytes), "r"(mbar) : "memory")

__device__ __forceinline__ void ldm_x4(uint32_t* r, uint32_t addr) {
    asm volatile("ldmatrix.sync.aligned.m8n8.x4.shared.b16 {%0,%1,%2,%3}, [%4];"
                 : "=r"(r[0]), "=r"(r[1]), "=r"(r[2]), "=r"(r[3]) : "r"(addr));
}
__device__ __forceinline__ void mma_f16acc(uint32_t* c, const uint32_t* a, const uint32_t* b) {
    asm volatile(
        "mma.sync.aligned.m16n8k16.row.col.f16.f16.f16.f16 "
        "{%0,%1}, {%2,%3,%4,%5}, {%6,%7}, {%0,%1};"
        : "+r"(c[0]), "+r"(c[1])
        : "r"(a[0]), "r"(a[1]), "r"(a[2]), "r"(a[3]), "r"(b[0]), "r"(b[1]));
}

__device__ __forceinline__ uint32_t h2u(__half2 h) {
    uint32_t u; __builtin_memcpy(&u, &h, 4); return u;
}
__device__ __forceinline__ uint4 pack8_h2(float4 lo, float4 hi) {
    uint4 u;
    u.x = h2u(__float22half2_rn(make_float2(lo.x, lo.y)));
    u.y = h2u(__float22half2_rn(make_float2(lo.z, lo.w)));
    u.z = h2u(__float22half2_rn(make_float2(hi.x, hi.y)));
    u.w = h2u(__float22half2_rn(make_float2(hi.z, hi.w)));
    return u;
}

// ---------------------------------------------------------------- fused prep
// One thread handles 8 consecutive k-dims (16B aligned group -> the SW128
// swizzle XOR (bits 4-6 only) keeps the 16B block contiguous).
// Blocks [0, NA): A side (NI*16 threads). Blocks [NA, NA+NB): B side (NC*16).
#define NA (NI * 16 / 256)          // 1024
#define NB (NC * 16 / 256)          // 256

__global__ void prep_kernel(const float* __restrict__ x,
                            const float* __restrict__ centers,
                            const float* __restrict__ sigmas) {
    int tid = threadIdx.x;
    if (blockIdx.x < NA) {
        int idx = blockIdx.x * 256 + tid;        // [0, NI*16)
        if (idx < NI) g_score[idx] = 0.f;
        int n  = idx >> 4;
        int d0 = (idx & 15) * 8;                 // 0..120, multiple of 8
        float4 lo = *(const float4*)(x + n * ND + d0);
        float4 hi = *(const float4*)(x + n * ND + d0 + 4);
        uint32_t sw = ((uint32_t)(n & 7)) << 4;
        int kch = d0 >> 6, e0 = d0 & 63;
        uint32_t off = ((uint32_t)(2 * e0)) ^ sw;    // 16B aligned
        // x^2 chunk
        float4 lo2 = make_float4(lo.x * lo.x, lo.y * lo.y, lo.z * lo.z, lo.w * lo.w);
        float4 hi2 = make_float4(hi.x * hi.x, hi.y * hi.y, hi.z * hi.z, hi.w * hi.w);
        *(uint4*)(g_A + ((size_t)kch * NI + n) * CHUNKB + off) = pack8_h2(lo2, hi2);
        // x chunk
        *(uint4*)(g_A + ((size_t)(2 + kch) * NI + n) * CHUNKB + off) = pack8_h2(lo, hi);
    } else {
        int idx = (blockIdx.x - NA) * 256 + tid; // [0, NC*16)
        int c  = idx >> 4;
        int d0 = (idx & 15) * 8;
        float4 clo = *(const float4*)(centers + c * ND + d0);
        float4 chi = *(const float4*)(centers + c * ND + d0 + 4);
        float4 slo = *(const float4*)(sigmas  + c * ND + d0);
        float4 shi = *(const float4*)(sigmas  + c * ND + d0 + 4);
        float il[8], cv[8], sv[8];
        cv[0]=clo.x; cv[1]=clo.y; cv[2]=clo.z; cv[3]=clo.w;
        cv[4]=chi.x; cv[5]=chi.y; cv[6]=chi.z; cv[7]=chi.w;
        sv[0]=slo.x; sv[1]=slo.y; sv[2]=slo.z; sv[3]=slo.w;
        sv[4]=shi.x; sv[5]=shi.y; sv[6]=shi.z; sv[7]=shi.w;
        float acc = 0.f;
        #pragma unroll
        for (int i = 0; i < 8; i++) {
            il[i] = 1.0f / (2.0f * sv[i] * sv[i]);
            acc = fmaf(cv[i] * cv[i], il[i], acc);
        }
        uint32_t sw = ((uint32_t)(c & 7)) << 4;
        int kch = d0 >> 6, e0 = d0 & 63;
        uint32_t off = ((uint32_t)(2 * e0)) ^ sw;
        float4 ilo = make_float4(il[0], il[1], il[2], il[3]);
        float4 ihi = make_float4(il[4], il[5], il[6], il[7]);
        *(uint4*)(g_B + ((size_t)kch * NC + c) * CHUNKB + off) = pack8_h2(ilo, ihi);
        float4 xlo = make_float4(-2.f*cv[0]*il[0], -2.f*cv[1]*il[1], -2.f*cv[2]*il[2], -2.f*cv[3]*il[3]);
        float4 xhi = make_float4(-2.f*cv[4]*il[4], -2.f*cv[5]*il[5], -2.f*cv[6]*il[6], -2.f*cv[7]*il[7]);
        *(uint4*)(g_B + ((size_t)(2 + kch) * NC + c) * CHUNKB + off) = pack8_h2(xlo, xhi);
        // csum: reduce over the 16 lanes sharing this c (lane bits 0-3)
        #pragma unroll
        for (int m = 1; m < 16; m <<= 1) acc += __shfl_xor_sync(0xffffffffu, acc, m);
        if ((idx & 15) == 0) g_csum[c] = acc;
    }
}

// ---------------------------------------------------------------- main kernel
__global__ void __launch_bounds__(256, 3)
rbf_mma_kernel(const float* __restrict__ x,
               const float* __restrict__ centers,
               const float* __restrict__ sigmas,
               const float* __restrict__ w_lin) {
    extern __shared__ char smem[];
    const uint32_t smem_base = smem_u32(smem);
    const int tid  = threadIdx.x;
    const int lane = tid & 31;
    const int wid  = tid >> 5;
    const int wm   = wid >> 2;      // 0..1  (M)
    const int wn   = wid & 3;       // 0..3  (N)
    const int bn   = blockIdx.x;    // center tile
    const int bm   = blockIdx.y;    // input tile

    if (tid == 0) {
        MBAR_INIT(smem_base + 0, 1);
        MBAR_INIT(smem_base + 8, 1);
    }
    __syncthreads();

    auto issue_stage = [&](int st, int kiter) {
        uint32_t mb = smem_base + st * 8;
        MBAR_EXPECT_TX(mb, STAGE_BYTES);
        const uint8_t* srcA = g_A + ((size_t)kiter * NI + bm * BM) * CHUNKB;
        const uint8_t* srcB = g_B + ((size_t)kiter * NC + bn * BN) * CHUNKB;
        CP_BULK(smem_base + SM_A(st), (const void*)srcA, A_TILE_BYTES, mb);
        CP_BULK(smem_base + SM_B(st), (const void*)srcB, B_TILE_BYTES, mb);
    };

    if (tid == 0) {
        issue_stage(0, 0);
        issue_stage(1, 1);
    }

    // fp16 accumulators: 2 regs per m16n8 tile -> 32 regs
    uint32_t acc[4][4][2];
    #pragma unroll
    for (int mt = 0; mt < 4; mt++)
        #pragma unroll
        for (int nt = 0; nt < 4; nt++) { acc[mt][nt][0] = 0u; acc[mt][nt][1] = 0u; }

    #pragma unroll 1
    for (int k = 0; k < KITERS; k++) {
        const int st = k & 1;
        MBAR_WAIT(smem_base + st * 8, (k >> 1) & 1);

        const uint32_t aBase = smem_base + SM_A(st);
        const uint32_t bBase = smem_base + SM_B(st);
        #pragma unroll
        for (int kc = 0; kc < 4; kc++) {           // 4 x k16 per stage
            uint32_t a[4][4], b[4][2];
            #pragma unroll
            for (int mt = 0; mt < 4; mt++) {
                int row = wm * 64 + mt * 16 + (lane & 15);
                uint32_t boff = kc * 32 + ((lane >> 4) << 4);
                uint32_t addr = aBase + row * CHUNKB + (boff ^ ((row & 7) << 4));
                ldm_x4(a[mt], addr);
            }
            #pragma unroll
            for (int p = 0; p < 2; p++) {
                int g = lane >> 3;            // 0..3: {t0 k0, t0 k8, t1 k0, t1 k8}
                int trow = wn * 32 + p * 16 + (g >> 1) * 8 + (lane & 7);
                uint32_t boff = kc * 32 + ((g & 1) << 4);
                uint32_t addr = bBase + trow * CHUNKB + (boff ^ ((trow & 7) << 4));
                uint32_t bp[4];
                ldm_x4(bp, addr);
                b[2 * p][0] = bp[0]; b[2 * p][1] = bp[1];
                b[2 * p + 1][0] = bp[2]; b[2 * p + 1][1] = bp[3];
            }
            #pragma unroll
            for (int mt = 0; mt < 4; mt++)
                #pragma unroll
                for (int nt = 0; nt < 4; nt++)
                    mma_f16acc(acc[mt][nt], a[mt], b[nt]);
        }

        // barrier only needed when this stage's buffer gets refilled
        if (k + NSTAGE < KITERS) {
            __syncthreads();
            if (tid == 0) issue_stage(st, k + NSTAGE);
        }
    }

    // ---------------- epilogue: p = partial d2 over 128 dims (lower bound).
    // Skip if p >= TSCREEN; else compute remaining 128 dims exactly (fp32).
    const int cBase = bn * BN + wn * 32;
    float cs[4][2];
    #pragma unroll
    for (int nt = 0; nt < 4; nt++)
        #pragma unroll
        for (int j = 0; j < 2; j++)
            cs[nt][j] = __ldg(&g_csum[cBase + nt * 8 + (lane & 3) * 2 + j]);

    float mn = 1e30f;
    #pragma unroll
    for (int mt = 0; mt < 4; mt++)
        #pragma unroll
        for (int nt = 0; nt < 4; nt++)
            #pragma unroll
            for (int h = 0; h < 2; h++) {
                __half2 hv = *reinterpret_cast<__half2*>(&acc[mt][nt][h]);
                mn = fminf(mn, __low2float(hv)  + cs[nt][0]);
                mn = fminf(mn, __high2float(hv) + cs[nt][1]);
            }

    if (__any_sync(0xffffffffu, mn < TSCREEN)) {    // ~3% of warps
        float rs[4][2];
        #pragma unroll
        for (int mt = 0; mt < 4; mt++) { rs[mt][0] = 0.f; rs[mt][1] = 0.f; }
        #pragma unroll 1
        for (int mt = 0; mt < 4; mt++)
            #pragma unroll 1
            for (int nt = 0; nt < 4; nt++)
                #pragma unroll 1
                for (int h = 0; h < 2; h++) {
                    __half2 hv = *reinterpret_cast<__half2*>(&acc[mt][nt][h]);
                    float pv[2] = { __low2float(hv)  + cs[nt][0],
                                    __high2float(hv) + cs[nt][1] };
                    #pragma unroll 1
                    for (int j = 0; j < 2; j++) {
                        if (pv[j] < TSCREEN) {
                            int row = bm * BM + wm * 64 + mt * 16 + h * 8 + (lane >> 2);
                            int col = cBase + nt * 8 + (lane & 3) * 2 + j;
                            float rest = 0.f;
                            #pragma unroll 4
                            for (int d = KD; d < ND; d++) {
                                float xv = x[row * ND + d];
                                float cv = centers[col * ND + d];
                                float sv = sigmas[col * ND + d];
                                float df = xv - cv;
                                rest += (df * df) / (2.0f * sv * sv);
                            }
                            float d2 = pv[j] + rest;
                            if (d2 < 60.f)
                                rs[mt][h] = fmaf(expf(-d2), __ldg(&w_lin[col]), rs[mt][h]);
                        }
                    }
                }
        #pragma unroll
        for (int mt = 0; mt < 4; mt++)
            #pragma unroll
            for (int h = 0; h < 2; h++) {
                float v = rs[mt][h];
                v += __shfl_xor_sync(0xffffffffu, v, 1);
                v += __shfl_xor_sync(0xffffffffu, v, 2);
                if ((lane & 3) == 0)
                    atomicAdd(&g_score[bm * BM + wm * 64 + mt * 16 + h * 8 + (lane >> 2)], v);
            }
    }
    // fast path: skipped mass bounded; g_score pre-zeroed
}

__global__ void finalize_kernel(const float* __restrict__ b_lin,
                                float* __restrict__ out) {
    int n = blockIdx.x * blockDim.x + threadIdx.x;
    if (n < NI) {
        float s = g_score[n] + b_lin[0];
        out[n] = 1.0f / (1.0f + __expf(-s));
    }
}

// ---------------------------------------------------------------- launch
extern "C" void kernel_launch(void* const* d_in, const int* in_sizes, int n_in,
                              void* d_out, int out_size) {
    const float* x       = (const float*)d_in[0];
    const float* centers = (const float*)d_in[1];
    const float* sigmas  = (const float*)d_in[2];
    const float* w_lin   = (const float*)d_in[3];
    const float* b_lin   = (const float*)d_in[4];
    float* out = (float*)d_out;

    cudaFuncSetAttribute(rbf_mma_kernel,
                         cudaFuncAttributeMaxDynamicSharedMemorySize, SMEM_BYTES);

    prep_kernel<<<NA + NB, 256>>>(x, centers, sigmas);
    dim3 grid(NC / BN, NI / BM);   // (32, 128)
    rbf_mma_kernel<<<grid, 256, SMEM_BYTES>>>(x, centers, sigmas, w_lin);
    finalize_kernel<<<NI / 256, 256>>>(b_lin, out);
}